// round 8
// baseline (speedup 1.0000x reference)
#include <cuda_runtime.h>
#include <cuda_bf16.h>
#include <cstdint>
#include <cstddef>

#define N_NODES 20000
#define N_EDGES 320000
#define M_PAD   20224          // 158 * 128
#define F1 1152
#define F2 576
#define F3 288

#define KCAT1 (6 * F1)         // 6912
#define KCAT2 (5 * F1)         // 5760
#define KCAT3 (5 * F2)         // 2880
#define N1PAD 1152             // 9 * 128
#define N2PAD 640              // 5 * 128
#define N3PAD 384              // 3 * 128

// ---------------- scratch (device globals; allocation-free) ----------------
// ping-pong A-cat buffers (hi/lo bf16 split); all intermediates live here
__device__ __nv_bfloat16 g_AhiA[(size_t)M_PAD * KCAT1];
__device__ __nv_bfloat16 g_AloA[(size_t)M_PAD * KCAT1];
__device__ __nv_bfloat16 g_AhiB[(size_t)M_PAD * KCAT2];
__device__ __nv_bfloat16 g_AloB[(size_t)M_PAD * KCAT2];

__device__ __nv_bfloat16 g_W1h[(size_t)N1PAD * KCAT1];
__device__ __nv_bfloat16 g_W1l[(size_t)N1PAD * KCAT1];
__device__ __nv_bfloat16 g_W2h[(size_t)N2PAD * KCAT2];
__device__ __nv_bfloat16 g_W2l[(size_t)N2PAD * KCAT2];
__device__ __nv_bfloat16 g_W3h[(size_t)N3PAD * KCAT3];
__device__ __nv_bfloat16 g_W3l[(size_t)N3PAD * KCAT3];

__device__ int   g_deg[N_NODES];
__device__ int   g_fill[N_NODES];
__device__ int   g_rowptr[N_NODES + 1];
__device__ int   g_colS[N_EDGES];
__device__ float g_dis[N_NODES];

// ---------------- PTX helpers (base sm_103 target only) ----------------
__device__ __forceinline__ uint32_t smem_u32(const void* p) {
    uint32_t a;
    asm("{ .reg .u64 t; cvta.to.shared.u64 t, %1; cvt.u32.u64 %0, t; }" : "=r"(a) : "l"(p));
    return a;
}

#define CP_ASYNC16(dst, src) \
    asm volatile("cp.async.cg.shared.global [%0], [%1], 16;" :: "r"(dst), "l"(src) : "memory")
#define CP_COMMIT() asm volatile("cp.async.commit_group;" ::: "memory")
#define CP_WAIT1()  asm volatile("cp.async.wait_group 1;" ::: "memory")

#define LDMATRIX_X4(r0, r1, r2, r3, addr) \
    asm volatile("ldmatrix.sync.aligned.m8n8.x4.shared.b16 {%0,%1,%2,%3}, [%4];" \
                 : "=r"(r0), "=r"(r1), "=r"(r2), "=r"(r3) : "r"(addr))

#define MMA_BF16(d, a, b) \
    asm volatile("mma.sync.aligned.m16n8k16.row.col.f32.bf16.bf16.f32 " \
                 "{%0,%1,%2,%3}, {%4,%5,%6,%7}, {%8,%9}, {%0,%1,%2,%3};" \
                 : "+f"((d)[0]), "+f"((d)[1]), "+f"((d)[2]), "+f"((d)[3]) \
                 : "r"((a)[0]), "r"((a)[1]), "r"((a)[2]), "r"((a)[3]), \
                   "r"((b)[0]), "r"((b)[1]))

// ---------------- graph setup ----------------
__global__ void zero_counts_kernel() {
    int i = blockIdx.x * blockDim.x + threadIdx.x;
    if (i < N_NODES) { g_deg[i] = 0; g_fill[i] = 0; }
}
__global__ void hist_kernel(const int* __restrict__ row, const int* __restrict__ col) {
    int e = blockIdx.x * blockDim.x + threadIdx.x;
    if (e < N_EDGES) {
        int r = row[e];
        if (r != col[e]) atomicAdd(&g_deg[r], 1);
    }
}
// scan + dis fused
__global__ void scan_kernel() {
    __shared__ int sums[1024];
    int t = threadIdx.x;
    const int CHUNK = (N_NODES + 1023) / 1024;
    int lo = t * CHUNK, hi = lo + CHUNK;
    if (hi > N_NODES) hi = N_NODES;
    int s = 0;
    for (int i = lo; i < hi; i++) s += g_deg[i];
    sums[t] = s;
    __syncthreads();
    for (int off = 1; off < 1024; off <<= 1) {
        int v = (t >= off) ? sums[t - off] : 0;
        __syncthreads();
        sums[t] += v;
        __syncthreads();
    }
    int run = (t == 0) ? 0 : sums[t - 1];
    for (int i = lo; i < hi; i++) {
        g_rowptr[i] = run;
        int d = g_deg[i];
        run += d;
        g_dis[i] = (d > 0) ? rsqrtf((float)d) : 0.0f;
    }
    if (t == 1023) g_rowptr[N_NODES] = sums[1023];
}
__global__ void scatter_kernel(const int* __restrict__ row, const int* __restrict__ col) {
    int e = blockIdx.x * blockDim.x + threadIdx.x;
    if (e < N_EDGES) {
        int r = row[e], c = col[e];
        if (r != c) {
            int pos = g_rowptr[r] + atomicAdd(&g_fill[r], 1);
            g_colS[pos] = c;
        }
    }
}

// ---------------- split / reconstruct helpers ----------------
__device__ __forceinline__ void split1(float v, __nv_bfloat16& h, __nv_bfloat16& l) {
    h = __float2bfloat16(v);
    l = __float2bfloat16(v - __bfloat162float(h));
}
// reconstruct 2 fp32 values from packed bf16x2 hi/lo words (bf16->f32 = <<16)
__device__ __forceinline__ float rec_lo(uint32_t h, uint32_t l) {
    return __uint_as_float(h << 16) + __uint_as_float(l << 16);
}
__device__ __forceinline__ float rec_hi(uint32_t h, uint32_t l) {
    return __uint_as_float(h & 0xffff0000u) + __uint_as_float(l & 0xffff0000u);
}

// weight transpose + split: W [Kcat x N] fp32 -> WT hi/lo [Npad x Kcat] bf16
__global__ void wsplit_kernel(const float* __restrict__ W, int Kcat, int N, int Npad,
                              __nv_bfloat16* __restrict__ hi,
                              __nv_bfloat16* __restrict__ lo) {
    __shared__ float tile[32][33];
    int k0 = blockIdx.x * 32, n0 = blockIdx.y * 32;
    int tx = threadIdx.x, ty = threadIdx.y;   // (32, 8)
#pragma unroll
    for (int r = 0; r < 32; r += 8) {
        int kk = k0 + ty + r, nn = n0 + tx;
        tile[ty + r][tx] = (kk < Kcat && nn < N) ? W[(size_t)kk * N + nn] : 0.0f;
    }
    __syncthreads();
#pragma unroll
    for (int r = 0; r < 32; r += 8) {
        int nn = n0 + ty + r, kk = k0 + tx;
        if (nn < Npad && kk < Kcat) {
            float v = tile[tx][ty + r];
            __nv_bfloat16 h, l;
            split1(v, h, l);
            hi[(size_t)nn * Kcat + kk] = h;
            lo[(size_t)nn * Kcat + kk] = l;
        }
    }
}

// ---------------- hi/lo-resident propagation ----------------
// Tx_out = alpha * (L~ Tx_in) - Tx_sub, all values stored as bf16 hi/lo pairs
// in the cat buffer (slice columns colIn/colSub/colOut). If TF32, Tx_in is the
// fp32 tensor tf instead (layer-1 first prop), and selfColOff>=0 additionally
// splits tf's own row into that slice. Pad rows (i>=N_NODES) write zeros.
// THREADS = F/8 exactly; each thread owns 8 contiguous features.
template <int F, int THREADS, bool TF32>
__global__ void prop_kernel(const float* __restrict__ tf,
                            __nv_bfloat16* __restrict__ hi,
                            __nv_bfloat16* __restrict__ lo,
                            int ldCat, int colIn, int colSub, int colOut,
                            float alpha, int selfColOff) {
    static_assert(THREADS * 8 == F, "exact fit required");
    constexpr int ECHUNK = 128;
    __shared__ int   s_col[ECHUNK];
    __shared__ float s_w[ECHUNK];

    int i = blockIdx.x;
    int tid = threadIdx.x;
    bool real = (i < N_NODES);
    int s0 = real ? g_rowptr[i] : 0;
    int s1 = real ? g_rowptr[i + 1] : 0;

    float a[8];
#pragma unroll
    for (int k = 0; k < 8; k++) a[k] = 0.f;

    int e = s0;
    while (e < s1) {
        int cnt = s1 - e; if (cnt > ECHUNK) cnt = ECHUNK;
        __syncthreads();
        for (int q = tid; q < cnt; q += THREADS) {
            int c = g_colS[e + q];
            s_col[q] = c;
            s_w[q] = g_dis[c];
        }
        __syncthreads();

        for (int q = 0; q < cnt; q++) {
            int c = s_col[q];
            float w = s_w[q];
            if (TF32) {
                const float4* tr = reinterpret_cast<const float4*>(tf) + (size_t)c * (F / 4) + tid * 2;
                float4 v0 = tr[0], v1 = tr[1];
                a[0] += w * v0.x; a[1] += w * v0.y; a[2] += w * v0.z; a[3] += w * v0.w;
                a[4] += w * v1.x; a[5] += w * v1.y; a[6] += w * v1.z; a[7] += w * v1.w;
            } else {
                size_t base = (size_t)c * ldCat + colIn + tid * 8;
                uint4 H = *reinterpret_cast<const uint4*>(hi + base);
                uint4 L = *reinterpret_cast<const uint4*>(lo + base);
                a[0] += w * rec_lo(H.x, L.x); a[1] += w * rec_hi(H.x, L.x);
                a[2] += w * rec_lo(H.y, L.y); a[3] += w * rec_hi(H.y, L.y);
                a[4] += w * rec_lo(H.z, L.z); a[5] += w * rec_hi(H.z, L.z);
                a[6] += w * rec_lo(H.w, L.w); a[7] += w * rec_hi(H.w, L.w);
            }
        }
        e += cnt;
    }

    float sc = real ? (-alpha * g_dis[i]) : 0.0f;
    float r[8];
#pragma unroll
    for (int k = 0; k < 8; k++) r[k] = sc * a[k];

    if (colSub >= 0) {
        size_t base = (size_t)i * ldCat + colSub + tid * 8;
        uint4 H = *reinterpret_cast<const uint4*>(hi + base);
        uint4 L = *reinterpret_cast<const uint4*>(lo + base);
        r[0] -= rec_lo(H.x, L.x); r[1] -= rec_hi(H.x, L.x);
        r[2] -= rec_lo(H.y, L.y); r[3] -= rec_hi(H.y, L.y);
        r[4] -= rec_lo(H.z, L.z); r[5] -= rec_hi(H.z, L.z);
        r[6] -= rec_lo(H.w, L.w); r[7] -= rec_hi(H.w, L.w);
    }

    {
        __nv_bfloat162 hp[4], lp[4];
#pragma unroll
        for (int k = 0; k < 4; k++) {
            __nv_bfloat16 h0, l0, h1, l1;
            split1(r[2 * k], h0, l0);
            split1(r[2 * k + 1], h1, l1);
            hp[k] = __nv_bfloat162(h0, h1);
            lp[k] = __nv_bfloat162(l0, l1);
        }
        size_t ob = (size_t)i * ldCat + colOut + tid * 8;
        *reinterpret_cast<uint4*>(hi + ob) = *reinterpret_cast<uint4*>(hp);
        *reinterpret_cast<uint4*>(lo + ob) = *reinterpret_cast<uint4*>(lp);
    }

    if (TF32 && selfColOff >= 0) {
        float v[8];
        if (real) {
            const float4* me = reinterpret_cast<const float4*>(tf) + (size_t)i * (F / 4) + tid * 2;
            float4 v0 = me[0], v1 = me[1];
            v[0] = v0.x; v[1] = v0.y; v[2] = v0.z; v[3] = v0.w;
            v[4] = v1.x; v[5] = v1.y; v[6] = v1.z; v[7] = v1.w;
        } else {
#pragma unroll
            for (int k = 0; k < 8; k++) v[k] = 0.f;
        }
        __nv_bfloat162 hp[4], lp[4];
#pragma unroll
        for (int k = 0; k < 4; k++) {
            __nv_bfloat16 h0, l0, h1, l1;
            split1(v[2 * k], h0, l0);
            split1(v[2 * k + 1], h1, l1);
            hp[k] = __nv_bfloat162(h0, h1);
            lp[k] = __nv_bfloat162(l0, l1);
        }
        size_t ob = (size_t)i * ldCat + selfColOff + tid * 8;
        *reinterpret_cast<uint4*>(hi + ob) = *reinterpret_cast<uint4*>(hp);
        *reinterpret_cast<uint4*>(lo + ob) = *reinterpret_cast<uint4*>(lp);
    }
}

// ---------------- fused tri-product mma.sync GEMM ----------------
// d += Ahi*Bhi + Alo*Bhi + Ahi*Blo per k-tile (single K sweep).
// Epilogue: relu(d + bias); optional fp32 C write (may be nullptr);
// optional bf16 hi/lo split into next layer's cat slice 0.
// 128x128 CTA, 4 warps of 64x64, 3 stages XOR-swizzled, 1 sync/k-tile, 2 CTA/SM.
#define GBK     32
#define TILE_B  (128 * 64)                // 8192
#define STG_B   (4 * TILE_B)              // 32768: Ahi, Alo, Bhi, Blo
#define SMEM_TOTAL_GEMM (3 * STG_B)       // 98304

__device__ __forceinline__ uint32_t sw_off(int r, int c16) {
    return (uint32_t)(r * 64 + ((c16 ^ ((r >> 1) & 3)) * 16));
}

__global__ void __launch_bounds__(128, 2)
gemm_fused_kernel(const __nv_bfloat16* __restrict__ Ahi, const __nv_bfloat16* __restrict__ Alo,
                  const __nv_bfloat16* __restrict__ Bhi, const __nv_bfloat16* __restrict__ Blo,
                  const float* __restrict__ bias, float* __restrict__ C,
                  int N, int Kcat,
                  __nv_bfloat16* __restrict__ nextHi, __nv_bfloat16* __restrict__ nextLo,
                  int ldNext) {
    extern __shared__ char smem[];
    uint32_t sb = smem_u32(smem);
    int tid = threadIdx.x;
    int lane = tid & 31;
    int wid = tid >> 5;
    int bm = blockIdx.y * 128;
    int bn = blockIdx.x * 128;

    const int kt = Kcat / GBK;

    int wm = (wid & 1) * 64;
    int wn = (wid >> 1) * 64;

    float d[4][8][4];
#pragma unroll
    for (int i = 0; i < 4; i++)
#pragma unroll
        for (int j = 0; j < 8; j++)
#pragma unroll
            for (int q = 0; q < 4; q++) d[i][j][q] = 0.f;

    size_t ld = (size_t)Kcat * 2;   // bytes per row
    auto issue = [&](int it) {
        int kk = it * GBK;
        int s = it % 3;
        uint32_t base = sb + s * STG_B;
        const char* src[4] = {
            (const char*)(Ahi + (size_t)bm * Kcat + kk),
            (const char*)(Alo + (size_t)bm * Kcat + kk),
            (const char*)(Bhi + (size_t)bn * Kcat + kk),
            (const char*)(Blo + (size_t)bn * Kcat + kk)
        };
#pragma unroll
        for (int tIdx = 0; tIdx < 4; tIdx++) {
            uint32_t dst = base + tIdx * TILE_B;
            const char* g = src[tIdx];
#pragma unroll
            for (int i = 0; i < 4; i++) {
                int v = tid + i * 128;
                int r = v >> 2, p = v & 3;
                CP_ASYNC16(dst + sw_off(r, p), g + (size_t)r * ld + p * 16);
            }
        }
    };

    // prologue: 2 stages in flight
    issue(0); CP_COMMIT();
    if (kt > 1) issue(1);
    CP_COMMIT();

    int lrow = lane & 15;
    int lcol = (lane >> 4) * 8;

    for (int it = 0; it < kt; ++it) {
        CP_WAIT1();
        __syncthreads();                    // stage it%3 ready & all warps past it-1

        if (it + 2 < kt) issue(it + 2);     // writes stage (it+2)%3 == (it-1)%3: safe
        CP_COMMIT();

        int s = it % 3;
        uint32_t sAh = sb + s * STG_B;
        uint32_t sAl = sAh + TILE_B;
        uint32_t sBh = sAh + 2 * TILE_B;
        uint32_t sBl = sAh + 3 * TILE_B;

#pragma unroll
        for (int ks = 0; ks < GBK; ks += 16) {
            int cch = (ks + lcol) >> 3;     // 16B chunk index in row
            uint32_t ah[4][4], al[4][4], bh[8][2], bl[8][2];
#pragma unroll
            for (int i = 0; i < 4; i++) {
                int rr = wm + i * 16 + lrow;
                LDMATRIX_X4(ah[i][0], ah[i][1], ah[i][2], ah[i][3], sAh + sw_off(rr, cch));
            }
#pragma unroll
            for (int i = 0; i < 4; i++) {
                int rr = wm + i * 16 + lrow;
                LDMATRIX_X4(al[i][0], al[i][1], al[i][2], al[i][3], sAl + sw_off(rr, cch));
            }
#pragma unroll
            for (int jp = 0; jp < 4; jp++) {
                int rr = wn + jp * 16 + lrow;
                uint32_t q0, q1, q2, q3;
                LDMATRIX_X4(q0, q1, q2, q3, sBh + sw_off(rr, cch));
                bh[2 * jp][0] = q0; bh[2 * jp][1] = q2;
                bh[2 * jp + 1][0] = q1; bh[2 * jp + 1][1] = q3;
            }
#pragma unroll
            for (int jp = 0; jp < 4; jp++) {
                int rr = wn + jp * 16 + lrow;
                uint32_t q0, q1, q2, q3;
                LDMATRIX_X4(q0, q1, q2, q3, sBl + sw_off(rr, cch));
                bl[2 * jp][0] = q0; bl[2 * jp][1] = q2;
                bl[2 * jp + 1][0] = q1; bl[2 * jp + 1][1] = q3;
            }
#pragma unroll
            for (int i = 0; i < 4; i++)
#pragma unroll
                for (int j = 0; j < 8; j++) {
                    MMA_BF16(d[i][j], ah[i], bh[j]);
                    MMA_BF16(d[i][j], al[i], bh[j]);
                    MMA_BF16(d[i][j], ah[i], bl[j]);
                }
        }
    }

    // epilogue: bias + relu; optional fp32 write; optional hi/lo split for next layer
    int gr = lane >> 2;
    int gc = (lane & 3) * 2;
#pragma unroll
    for (int i = 0; i < 4; i++) {
#pragma unroll
        for (int j = 0; j < 8; j++) {
            int colb = bn + wn + j * 8 + gc;
            if (colb >= N) continue;
            float b0 = bias[colb], b1 = bias[colb + 1];
            int row0 = bm + wm + i * 16 + gr;
            int row1 = row0 + 8;

            bool ok0 = row0 < N_NODES;
            float v0x = ok0 ? fmaxf(d[i][j][0] + b0, 0.f) : 0.f;
            float v0y = ok0 ? fmaxf(d[i][j][1] + b1, 0.f) : 0.f;
            if (C && ok0) {
                float2 v; v.x = v0x; v.y = v0y;
                *reinterpret_cast<float2*>(&C[(size_t)row0 * N + colb]) = v;
            }
            if (nextHi) {
                __nv_bfloat16 hx, lx, hy, ly;
                split1(v0x, hx, lx); split1(v0y, hy, ly);
                size_t o = (size_t)row0 * ldNext + colb;
                *reinterpret_cast<__nv_bfloat162*>(nextHi + o) = __nv_bfloat162(hx, hy);
                *reinterpret_cast<__nv_bfloat162*>(nextLo + o) = __nv_bfloat162(lx, ly);
            }

            bool ok1 = row1 < N_NODES;
            float v1x = ok1 ? fmaxf(d[i][j][2] + b0, 0.f) : 0.f;
            float v1y = ok1 ? fmaxf(d[i][j][3] + b1, 0.f) : 0.f;
            if (C && ok1) {
                float2 v; v.x = v1x; v.y = v1y;
                *reinterpret_cast<float2*>(&C[(size_t)row1 * N + colb]) = v;
            }
            if (nextHi) {
                __nv_bfloat16 hx, lx, hy, ly;
                split1(v1x, hx, lx); split1(v1y, hy, ly);
                size_t o = (size_t)row1 * ldNext + colb;
                *reinterpret_cast<__nv_bfloat162*>(nextHi + o) = __nv_bfloat162(hx, hy);
                *reinterpret_cast<__nv_bfloat162*>(nextLo + o) = __nv_bfloat162(lx, ly);
            }
        }
    }
}

// ---------------- host orchestration ----------------
extern "C" void kernel_launch(void* const* d_in, const int* in_sizes, int n_in,
                              void* d_out, int out_size) {
    const float* x   = (const float*)d_in[0];
    const int*   row = (const int*)d_in[1];
    const int*   col = (const int*)d_in[2];
    const float* W1  = (const float*)d_in[3];
    const float* b1  = (const float*)d_in[4];
    const float* W2  = (const float*)d_in[5];
    const float* b2  = (const float*)d_in[6];
    const float* W3  = (const float*)d_in[7];
    const float* b3  = (const float*)d_in[8];
    float* out = (float*)d_out;

    __nv_bfloat16 *AhiA, *AloA, *AhiB, *AloB;
    __nv_bfloat16 *W1h, *W1l, *W2h, *W2l, *W3h, *W3l;
    cudaGetSymbolAddress((void**)&AhiA, g_AhiA);
    cudaGetSymbolAddress((void**)&AloA, g_AloA);
    cudaGetSymbolAddress((void**)&AhiB, g_AhiB);
    cudaGetSymbolAddress((void**)&AloB, g_AloB);
    cudaGetSymbolAddress((void**)&W1h, g_W1h);
    cudaGetSymbolAddress((void**)&W1l, g_W1l);
    cudaGetSymbolAddress((void**)&W2h, g_W2h);
    cudaGetSymbolAddress((void**)&W2l, g_W2l);
    cudaGetSymbolAddress((void**)&W3h, g_W3h);
    cudaGetSymbolAddress((void**)&W3l, g_W3l);

    cudaFuncSetAttribute(gemm_fused_kernel,
                         cudaFuncAttributeMaxDynamicSharedMemorySize, SMEM_TOTAL_GEMM);

    // ---- graph setup (4 launches) ----
    zero_counts_kernel<<<(N_NODES + 255) / 256, 256>>>();
    hist_kernel<<<(N_EDGES + 255) / 256, 256>>>(row, col);
    scan_kernel<<<1, 1024>>>();           // also computes dis
    scatter_kernel<<<(N_EDGES + 255) / 256, 256>>>(row, col);

    // ---- weight conversions (~50us total) ----
    {
        dim3 g1((KCAT1 + 31) / 32, (N1PAD + 31) / 32);
        wsplit_kernel<<<g1, dim3(32, 8)>>>(W1, KCAT1, F1, N1PAD, W1h, W1l);
        dim3 g2((KCAT2 + 31) / 32, (N2PAD + 31) / 32);
        wsplit_kernel<<<g2, dim3(32, 8)>>>(W2, KCAT2, F2, N2PAD, W2h, W2l);
        dim3 g3((KCAT3 + 31) / 32, (N3PAD + 31) / 32);
        wsplit_kernel<<<g3, dim3(32, 8)>>>(W3, KCAT3, F3, N3PAD, W3h, W3l);
    }

    // ================= Layer 1: 1152 -> 1152, K=6, Kcat=6912 =================
    // prop1 gathers fp32 x and also splits x itself into slice 0
    prop_kernel<F1, 144, true ><<<M_PAD, 144>>>(x, AhiA, AloA, KCAT1, 0,      -1,     1 * F1, 1.0f, 0);
    prop_kernel<F1, 144, false><<<M_PAD, 144>>>(nullptr, AhiA, AloA, KCAT1, 1 * F1, 0,      2 * F1, 2.0f, -1);
    prop_kernel<F1, 144, false><<<M_PAD, 144>>>(nullptr, AhiA, AloA, KCAT1, 2 * F1, 1 * F1, 3 * F1, 2.0f, -1);
    prop_kernel<F1, 144, false><<<M_PAD, 144>>>(nullptr, AhiA, AloA, KCAT1, 3 * F1, 2 * F1, 4 * F1, 2.0f, -1);
    prop_kernel<F1, 144, false><<<M_PAD, 144>>>(nullptr, AhiA, AloA, KCAT1, 4 * F1, 3 * F1, 5 * F1, 2.0f, -1);
    {
        dim3 grid(N1PAD / 128, M_PAD / 128);
        gemm_fused_kernel<<<grid, 128, SMEM_TOTAL_GEMM>>>(
            AhiA, AloA, W1h, W1l, b1, nullptr, F1, KCAT1, AhiB, AloB, KCAT2);
    }

    // ================= Layer 2: 1152 -> 576, K=5, Kcat=5760 =================
    prop_kernel<F1, 144, false><<<M_PAD, 144>>>(nullptr, AhiB, AloB, KCAT2, 0,      -1,     1 * F1, 1.0f, -1);
    prop_kernel<F1, 144, false><<<M_PAD, 144>>>(nullptr, AhiB, AloB, KCAT2, 1 * F1, 0,      2 * F1, 2.0f, -1);
    prop_kernel<F1, 144, false><<<M_PAD, 144>>>(nullptr, AhiB, AloB, KCAT2, 2 * F1, 1 * F1, 3 * F1, 2.0f, -1);
    prop_kernel<F1, 144, false><<<M_PAD, 144>>>(nullptr, AhiB, AloB, KCAT2, 3 * F1, 2 * F1, 4 * F1, 2.0f, -1);
    {
        dim3 grid(N2PAD / 128, M_PAD / 128);
        gemm_fused_kernel<<<grid, 128, SMEM_TOTAL_GEMM>>>(
            AhiB, AloB, W2h, W2l, b2, nullptr, F2, KCAT2, AhiA, AloA, KCAT3);
    }

    // ================= Layer 3: 576 -> 288, K=5, Kcat=2880 =================
    prop_kernel<F2, 72, false><<<M_PAD, 72>>>(nullptr, AhiA, AloA, KCAT3, 0,      -1,     1 * F2, 1.0f, -1);
    prop_kernel<F2, 72, false><<<M_PAD, 72>>>(nullptr, AhiA, AloA, KCAT3, 1 * F2, 0,      2 * F2, 2.0f, -1);
    prop_kernel<F2, 72, false><<<M_PAD, 72>>>(nullptr, AhiA, AloA, KCAT3, 2 * F2, 1 * F2, 3 * F2, 2.0f, -1);
    prop_kernel<F2, 72, false><<<M_PAD, 72>>>(nullptr, AhiA, AloA, KCAT3, 3 * F2, 2 * F2, 4 * F2, 2.0f, -1);
    {
        dim3 grid(N3PAD / 128, M_PAD / 128);
        gemm_fused_kernel<<<grid, 128, SMEM_TOTAL_GEMM>>>(
            AhiA, AloA, W3h, W3l, b3, out, F3, KCAT3, nullptr, nullptr, 0);
    }
}

// round 9
// speedup vs baseline: 1.4740x; 1.4740x over previous
#include <cuda_runtime.h>
#include <cuda_bf16.h>
#include <cstdint>
#include <cstddef>

#define N_NODES 20000
#define N_EDGES 320000
#define M_PAD   20224          // 158 * 128
#define F1 1152
#define F2 576
#define F3 288

#define KCAT1 (6 * F1)         // 6912
#define KCAT2 (5 * F1)         // 5760
#define KCAT3 (5 * F2)         // 2880
#define N1PAD 1152             // 9 * 128
#define N2PAD 640              // 5 * 128
#define N3PAD 384              // 3 * 128

// ---------------- scratch (device globals; allocation-free) ----------------
__device__ float g_bufA[N_NODES * F1];
__device__ float g_bufB[N_NODES * F1];
__device__ float g_bufC[N_NODES * F1];
__device__ float g_acc1[N_NODES * F1];
__device__ float g_acc2[N_NODES * F2];

// ping-pong A-cat buffers (avoid GEMM read/write aliasing across layers)
__device__ __nv_bfloat16 g_AhiA[(size_t)M_PAD * KCAT1];
__device__ __nv_bfloat16 g_AloA[(size_t)M_PAD * KCAT1];
__device__ __nv_bfloat16 g_AhiB[(size_t)M_PAD * KCAT2];
__device__ __nv_bfloat16 g_AloB[(size_t)M_PAD * KCAT2];

__device__ __nv_bfloat16 g_W1h[(size_t)N1PAD * KCAT1];
__device__ __nv_bfloat16 g_W1l[(size_t)N1PAD * KCAT1];
__device__ __nv_bfloat16 g_W2h[(size_t)N2PAD * KCAT2];
__device__ __nv_bfloat16 g_W2l[(size_t)N2PAD * KCAT2];
__device__ __nv_bfloat16 g_W3h[(size_t)N3PAD * KCAT3];
__device__ __nv_bfloat16 g_W3l[(size_t)N3PAD * KCAT3];

__device__ int   g_deg[N_NODES];
__device__ int   g_fill[N_NODES];
__device__ int   g_rowptr[N_NODES + 1];
__device__ int   g_colS[N_EDGES];
__device__ float g_dis[N_NODES];

// ---------------- PTX helpers (base sm_103 target only) ----------------
__device__ __forceinline__ uint32_t smem_u32(const void* p) {
    uint32_t a;
    asm("{ .reg .u64 t; cvta.to.shared.u64 t, %1; cvt.u32.u64 %0, t; }" : "=r"(a) : "l"(p));
    return a;
}

#define CP_ASYNC16(dst, src) \
    asm volatile("cp.async.cg.shared.global [%0], [%1], 16;" :: "r"(dst), "l"(src) : "memory")
#define CP_COMMIT() asm volatile("cp.async.commit_group;" ::: "memory")
#define CP_WAIT1()  asm volatile("cp.async.wait_group 1;" ::: "memory")

#define LDMATRIX_X4(r0, r1, r2, r3, addr) \
    asm volatile("ldmatrix.sync.aligned.m8n8.x4.shared.b16 {%0,%1,%2,%3}, [%4];" \
                 : "=r"(r0), "=r"(r1), "=r"(r2), "=r"(r3) : "r"(addr))

#define MMA_BF16(d, a, b) \
    asm volatile("mma.sync.aligned.m16n8k16.row.col.f32.bf16.bf16.f32 " \
                 "{%0,%1,%2,%3}, {%4,%5,%6,%7}, {%8,%9}, {%0,%1,%2,%3};" \
                 : "+f"((d)[0]), "+f"((d)[1]), "+f"((d)[2]), "+f"((d)[3]) \
                 : "r"((a)[0]), "r"((a)[1]), "r"((a)[2]), "r"((a)[3]), \
                   "r"((b)[0]), "r"((b)[1]))

// ---------------- graph setup ----------------
__global__ void zero_counts_kernel() {
    int i = blockIdx.x * blockDim.x + threadIdx.x;
    if (i < N_NODES) { g_deg[i] = 0; g_fill[i] = 0; }
}
__global__ void hist_kernel(const int* __restrict__ row, const int* __restrict__ col) {
    int e = blockIdx.x * blockDim.x + threadIdx.x;
    if (e < N_EDGES) {
        int r = row[e];
        if (r != col[e]) atomicAdd(&g_deg[r], 1);
    }
}
// scan + dis fused
__global__ void scan_kernel() {
    __shared__ int sums[1024];
    int t = threadIdx.x;
    const int CHUNK = (N_NODES + 1023) / 1024;
    int lo = t * CHUNK, hi = lo + CHUNK;
    if (hi > N_NODES) hi = N_NODES;
    int s = 0;
    for (int i = lo; i < hi; i++) s += g_deg[i];
    sums[t] = s;
    __syncthreads();
    for (int off = 1; off < 1024; off <<= 1) {
        int v = (t >= off) ? sums[t - off] : 0;
        __syncthreads();
        sums[t] += v;
        __syncthreads();
    }
    int run = (t == 0) ? 0 : sums[t - 1];
    for (int i = lo; i < hi; i++) {
        g_rowptr[i] = run;
        int d = g_deg[i];
        run += d;
        g_dis[i] = (d > 0) ? rsqrtf((float)d) : 0.0f;
    }
    if (t == 1023) g_rowptr[N_NODES] = sums[1023];
}
__global__ void scatter_kernel(const int* __restrict__ row, const int* __restrict__ col) {
    int e = blockIdx.x * blockDim.x + threadIdx.x;
    if (e < N_EDGES) {
        int r = row[e], c = col[e];
        if (r != c) {
            int pos = g_rowptr[r] + atomicAdd(&g_fill[r], 1);
            g_colS[pos] = c;
        }
    }
}

// ---------------- split helpers ----------------
__device__ __forceinline__ void split1(float v, __nv_bfloat16& h, __nv_bfloat16& l) {
    h = __float2bfloat16(v);
    l = __float2bfloat16(v - __bfloat162float(h));
}

// weight transpose + split: W [Kcat x N] fp32 -> WT hi/lo [Npad x Kcat] bf16
__global__ void wsplit_kernel(const float* __restrict__ W, int Kcat, int N, int Npad,
                              __nv_bfloat16* __restrict__ hi,
                              __nv_bfloat16* __restrict__ lo) {
    __shared__ float tile[32][33];
    int k0 = blockIdx.x * 32, n0 = blockIdx.y * 32;
    int tx = threadIdx.x, ty = threadIdx.y;   // (32, 8)
#pragma unroll
    for (int r = 0; r < 32; r += 8) {
        int kk = k0 + ty + r, nn = n0 + tx;
        tile[ty + r][tx] = (kk < Kcat && nn < N) ? W[(size_t)kk * N + nn] : 0.0f;
    }
    __syncthreads();
#pragma unroll
    for (int r = 0; r < 32; r += 8) {
        int nn = n0 + ty + r, kk = k0 + tx;
        if (nn < Npad && kk < Kcat) {
            float v = tile[tx][ty + r];
            __nv_bfloat16 h, l;
            split1(v, h, l);
            hi[(size_t)nn * Kcat + kk] = h;
            lo[(size_t)nn * Kcat + kk] = l;
        }
    }
}

// ---------------- propagation with fused bf16 split of the output ----------
// (R7 proven form) out = alpha * (L~ t) - sub (out may be nullptr);
// writes hi/lo split into cat slice colOff; if selfColOff >= 0, also splits
// this block's own row of t into cat slice selfColOff. Pad rows write zeros.
template <int F, int THREADS>
__global__ void prop_kernel(const float* __restrict__ t,
                            const float* __restrict__ sub,
                            float* __restrict__ out,
                            __nv_bfloat16* __restrict__ hi,
                            __nv_bfloat16* __restrict__ lo,
                            int ldCat, int colOff, float alpha, int selfColOff) {
    constexpr int F4 = F / 4;
    constexpr int NF = F4 / THREADS;
    static_assert(NF * THREADS == F4, "exact fit required");
    constexpr int ECHUNK = 128;
    __shared__ int   s_col[ECHUNK];
    __shared__ float s_w[ECHUNK];

    int i = blockIdx.x;
    int tid = threadIdx.x;
    bool real = (i < N_NODES);
    int s0 = real ? g_rowptr[i] : 0;
    int s1 = real ? g_rowptr[i + 1] : 0;

    float ax[NF], ay[NF], az[NF], aw[NF];
#pragma unroll
    for (int j = 0; j < NF; j++) { ax[j] = 0.f; ay[j] = 0.f; az[j] = 0.f; aw[j] = 0.f; }

    int e = s0;
    while (e < s1) {
        int cnt = s1 - e; if (cnt > ECHUNK) cnt = ECHUNK;
        __syncthreads();
        for (int q = tid; q < cnt; q += THREADS) {
            int c = g_colS[e + q];
            s_col[q] = c;
            s_w[q] = g_dis[c];
        }
        __syncthreads();

        int q = 0;
        for (; q + 2 <= cnt; q += 2) {
            int c0 = s_col[q], c1 = s_col[q + 1];
            float w0 = s_w[q], w1 = s_w[q + 1];
            const float4* t0 = reinterpret_cast<const float4*>(t) + (size_t)c0 * F4;
            const float4* t1 = reinterpret_cast<const float4*>(t) + (size_t)c1 * F4;
#pragma unroll
            for (int j = 0; j < NF; j++) {
                int f = tid + j * THREADS;
                float4 v0 = t0[f];
                float4 v1 = t1[f];
                ax[j] += w0 * v0.x + w1 * v1.x;
                ay[j] += w0 * v0.y + w1 * v1.y;
                az[j] += w0 * v0.z + w1 * v1.z;
                aw[j] += w0 * v0.w + w1 * v1.w;
            }
        }
        if (q < cnt) {
            int c = s_col[q];
            float s = s_w[q];
            const float4* tr = reinterpret_cast<const float4*>(t) + (size_t)c * F4;
#pragma unroll
            for (int j = 0; j < NF; j++) {
                int f = tid + j * THREADS;
                float4 v = tr[f];
                ax[j] += s * v.x; ay[j] += s * v.y;
                az[j] += s * v.z; aw[j] += s * v.w;
            }
        }
        e += cnt;
    }

    float sc = real ? (-alpha * g_dis[i]) : 0.0f;
    float4* orow = (real && out) ? (reinterpret_cast<float4*>(out) + (size_t)i * F4) : nullptr;
    const float4* srow = (real && sub)
        ? (reinterpret_cast<const float4*>(sub) + (size_t)i * F4) : nullptr;
#pragma unroll
    for (int j = 0; j < NF; j++) {
        int f = tid + j * THREADS;
        float4 r;
        r.x = sc * ax[j]; r.y = sc * ay[j]; r.z = sc * az[j]; r.w = sc * aw[j];
        if (srow) {
            float4 sv = srow[f];
            r.x -= sv.x; r.y -= sv.y; r.z -= sv.z; r.w -= sv.w;
        }
        if (orow) orow[f] = r;
        __nv_bfloat16 hx, lx, hy, ly, hz, lz, hw, lw;
        split1(r.x, hx, lx); split1(r.y, hy, ly);
        split1(r.z, hz, lz); split1(r.w, hw, lw);
        size_t o = (size_t)i * ldCat + colOff + (size_t)f * 4;
        __nv_bfloat162* hp = reinterpret_cast<__nv_bfloat162*>(hi + o);
        __nv_bfloat162* lp = reinterpret_cast<__nv_bfloat162*>(lo + o);
        hp[0] = __nv_bfloat162(hx, hy); hp[1] = __nv_bfloat162(hz, hw);
        lp[0] = __nv_bfloat162(lx, ly); lp[1] = __nv_bfloat162(lz, lw);
    }

    // fused Tx0 split (replaces convert kernel)
    if (selfColOff >= 0) {
        const float4* me = real ? (reinterpret_cast<const float4*>(t) + (size_t)i * F4) : nullptr;
#pragma unroll
        for (int j = 0; j < NF; j++) {
            int f = tid + j * THREADS;
            float4 v = me ? me[f] : make_float4(0.f, 0.f, 0.f, 0.f);
            __nv_bfloat16 hx, lx, hy, ly, hz, lz, hw, lw;
            split1(v.x, hx, lx); split1(v.y, hy, ly);
            split1(v.z, hz, lz); split1(v.w, hw, lw);
            size_t o = (size_t)i * ldCat + selfColOff + (size_t)f * 4;
            __nv_bfloat162* hp = reinterpret_cast<__nv_bfloat162*>(hi + o);
            __nv_bfloat162* lp = reinterpret_cast<__nv_bfloat162*>(lo + o);
            hp[0] = __nv_bfloat162(hx, hy); hp[1] = __nv_bfloat162(hz, hw);
            lp[0] = __nv_bfloat162(lx, ly); lp[1] = __nv_bfloat162(lz, lw);
        }
    }
}

// ---------------- fused tri-product mma.sync GEMM ----------------
// d += Ahi*Bhi + Alo*Bhi + Ahi*Blo per k-tile (single K sweep).
// Product-interleaved fragment loading: load(ah,bh)->MMA hh; load(al)->MMA lh;
// load(bl)->MMA hl. Peak live fragments 48 regs (was 64) -> better scheduling.
// 128x128 CTA, 4 warps of 64x64, 3 stages XOR-swizzled, 1 sync/k-tile, 2 CTA/SM.
#define GBK     32
#define TILE_B  (128 * 64)                // 8192
#define STG_B   (4 * TILE_B)              // 32768: Ahi, Alo, Bhi, Blo
#define SMEM_TOTAL_GEMM (3 * STG_B)       // 98304

__device__ __forceinline__ uint32_t sw_off(int r, int c16) {
    return (uint32_t)(r * 64 + ((c16 ^ ((r >> 1) & 3)) * 16));
}

__global__ void __launch_bounds__(128, 2)
gemm_fused_kernel(const __nv_bfloat16* __restrict__ Ahi, const __nv_bfloat16* __restrict__ Alo,
                  const __nv_bfloat16* __restrict__ Bhi, const __nv_bfloat16* __restrict__ Blo,
                  const float* __restrict__ bias, float* __restrict__ C,
                  int N, int Kcat,
                  __nv_bfloat16* __restrict__ nextHi, __nv_bfloat16* __restrict__ nextLo,
                  int ldNext) {
    extern __shared__ char smem[];
    uint32_t sb = smem_u32(smem);
    int tid = threadIdx.x;
    int lane = tid & 31;
    int wid = tid >> 5;
    int bm = blockIdx.y * 128;
    int bn = blockIdx.x * 128;

    const int kt = Kcat / GBK;

    int wm = (wid & 1) * 64;
    int wn = (wid >> 1) * 64;

    float d[4][8][4];
#pragma unroll
    for (int i = 0; i < 4; i++)
#pragma unroll
        for (int j = 0; j < 8; j++)
#pragma unroll
            for (int q = 0; q < 4; q++) d[i][j][q] = 0.f;

    size_t ld = (size_t)Kcat * 2;   // bytes per row
    auto issue = [&](int it) {
        int kk = it * GBK;
        int s = it % 3;
        uint32_t base = sb + s * STG_B;
        const char* src[4] = {
            (const char*)(Ahi + (size_t)bm * Kcat + kk),
            (const char*)(Alo + (size_t)bm * Kcat + kk),
            (const char*)(Bhi + (size_t)bn * Kcat + kk),
            (const char*)(Blo + (size_t)bn * Kcat + kk)
        };
#pragma unroll
        for (int tIdx = 0; tIdx < 4; tIdx++) {
            uint32_t dst = base + tIdx * TILE_B;
            const char* g = src[tIdx];
#pragma unroll
            for (int i = 0; i < 4; i++) {
                int v = tid + i * 128;
                int r = v >> 2, p = v & 3;
                CP_ASYNC16(dst + sw_off(r, p), g + (size_t)r * ld + p * 16);
            }
        }
    };

    // prologue: 2 stages in flight
    issue(0); CP_COMMIT();
    if (kt > 1) issue(1);
    CP_COMMIT();

    int lrow = lane & 15;
    int lcol = (lane >> 4) * 8;

    // precomputed swizzle row offsets for this thread's fragments
    uint32_t arow[4], brow[4];
#pragma unroll
    for (int i = 0; i < 4; i++) {
        int rr = wm + i * 16 + lrow;
        arow[i] = (uint32_t)(rr * 64) | ((uint32_t)((rr >> 1) & 3) << 28);
    }
#pragma unroll
    for (int jp = 0; jp < 4; jp++) {
        int rr = wn + jp * 16 + lrow;
        brow[jp] = (uint32_t)(rr * 64) | ((uint32_t)((rr >> 1) & 3) << 28);
    }

    for (int it = 0; it < kt; ++it) {
        CP_WAIT1();
        __syncthreads();                    // stage it%3 ready & all warps past it-1

        if (it + 2 < kt) issue(it + 2);     // writes stage (it+2)%3 == (it-1)%3: safe
        CP_COMMIT();

        int s = it % 3;
        uint32_t sAh = sb + s * STG_B;
        uint32_t sAl = sAh + TILE_B;
        uint32_t sBh = sAh + 2 * TILE_B;
        uint32_t sBl = sAh + 3 * TILE_B;

#pragma unroll
        for (int ks = 0; ks < GBK; ks += 16) {
            uint32_t cch = (uint32_t)((ks + lcol) >> 3);   // 16B chunk index in row

            uint32_t ah[4][4], bh[8][2];
            // --- load ah + bh, then product hh ---
#pragma unroll
            for (int i = 0; i < 4; i++) {
                uint32_t off = (arow[i] & 0x0fffffffu) + ((cch ^ (arow[i] >> 28)) << 4);
                LDMATRIX_X4(ah[i][0], ah[i][1], ah[i][2], ah[i][3], sAh + off);
            }
#pragma unroll
            for (int jp = 0; jp < 4; jp++) {
                uint32_t off = (brow[jp] & 0x0fffffffu) + ((cch ^ (brow[jp] >> 28)) << 4);
                uint32_t q0, q1, q2, q3;
                LDMATRIX_X4(q0, q1, q2, q3, sBh + off);
                bh[2 * jp][0] = q0; bh[2 * jp][1] = q2;
                bh[2 * jp + 1][0] = q1; bh[2 * jp + 1][1] = q3;
            }
#pragma unroll
            for (int i = 0; i < 4; i++)
#pragma unroll
                for (int j = 0; j < 8; j++)
                    MMA_BF16(d[i][j], ah[i], bh[j]);

            // --- load al, product lh (reuses bh) ---
            {
                uint32_t al[4][4];
#pragma unroll
                for (int i = 0; i < 4; i++) {
                    uint32_t off = (arow[i] & 0x0fffffffu) + ((cch ^ (arow[i] >> 28)) << 4);
                    LDMATRIX_X4(al[i][0], al[i][1], al[i][2], al[i][3], sAl + off);
                }
#pragma unroll
                for (int i = 0; i < 4; i++)
#pragma unroll
                    for (int j = 0; j < 8; j++)
                        MMA_BF16(d[i][j], al[i], bh[j]);
            }

            // --- load bl, product hl (reuses ah) ---
            {
                uint32_t bl[8][2];
#pragma unroll
                for (int jp = 0; jp < 4; jp++) {
                    uint32_t off = (brow[jp] & 0x0fffffffu) + ((cch ^ (brow[jp] >> 28)) << 4);
                    uint32_t q0, q1, q2, q3;
                    LDMATRIX_X4(q0, q1, q2, q3, sBl + off);
                    bl[2 * jp][0] = q0; bl[2 * jp][1] = q2;
                    bl[2 * jp + 1][0] = q1; bl[2 * jp + 1][1] = q3;
                }
#pragma unroll
                for (int i = 0; i < 4; i++)
#pragma unroll
                    for (int j = 0; j < 8; j++)
                        MMA_BF16(d[i][j], ah[i], bl[j]);
            }
        }
    }

    // epilogue: bias + relu; optional fp32 write; optional hi/lo split for next layer
    int gr = lane >> 2;
    int gc = (lane & 3) * 2;
#pragma unroll
    for (int i = 0; i < 4; i++) {
#pragma unroll
        for (int j = 0; j < 8; j++) {
            int colb = bn + wn + j * 8 + gc;
            if (colb >= N) continue;
            float b0 = bias[colb], b1 = bias[colb + 1];
            int row0 = bm + wm + i * 16 + gr;
            int row1 = row0 + 8;

            bool ok0 = row0 < N_NODES;
            float v0x = ok0 ? fmaxf(d[i][j][0] + b0, 0.f) : 0.f;
            float v0y = ok0 ? fmaxf(d[i][j][1] + b1, 0.f) : 0.f;
            if (C && ok0) {
                float2 v; v.x = v0x; v.y = v0y;
                *reinterpret_cast<float2*>(&C[(size_t)row0 * N + colb]) = v;
            }
            if (nextHi) {
                __nv_bfloat16 hx, lx, hy, ly;
                split1(v0x, hx, lx); split1(v0y, hy, ly);
                size_t o = (size_t)row0 * ldNext + colb;
                *reinterpret_cast<__nv_bfloat162*>(nextHi + o) = __nv_bfloat162(hx, hy);
                *reinterpret_cast<__nv_bfloat162*>(nextLo + o) = __nv_bfloat162(lx, ly);
            }

            bool ok1 = row1 < N_NODES;
            float v1x = ok1 ? fmaxf(d[i][j][2] + b0, 0.f) : 0.f;
            float v1y = ok1 ? fmaxf(d[i][j][3] + b1, 0.f) : 0.f;
            if (C && ok1) {
                float2 v; v.x = v1x; v.y = v1y;
                *reinterpret_cast<float2*>(&C[(size_t)row1 * N + colb]) = v;
            }
            if (nextHi) {
                __nv_bfloat16 hx, lx, hy, ly;
                split1(v1x, hx, lx); split1(v1y, hy, ly);
                size_t o = (size_t)row1 * ldNext + colb;
                *reinterpret_cast<__nv_bfloat162*>(nextHi + o) = __nv_bfloat162(hx, hy);
                *reinterpret_cast<__nv_bfloat162*>(nextLo + o) = __nv_bfloat162(lx, ly);
            }
        }
    }
}

// ---------------- host orchestration ----------------
extern "C" void kernel_launch(void* const* d_in, const int* in_sizes, int n_in,
                              void* d_out, int out_size) {
    const float* x   = (const float*)d_in[0];
    const int*   row = (const int*)d_in[1];
    const int*   col = (const int*)d_in[2];
    const float* W1  = (const float*)d_in[3];
    const float* b1  = (const float*)d_in[4];
    const float* W2  = (const float*)d_in[5];
    const float* b2  = (const float*)d_in[6];
    const float* W3  = (const float*)d_in[7];
    const float* b3  = (const float*)d_in[8];
    float* out = (float*)d_out;

    float *acc1, *acc2, *bufA, *bufB, *bufC;
    __nv_bfloat16 *AhiA, *AloA, *AhiB, *AloB;
    __nv_bfloat16 *W1h, *W1l, *W2h, *W2l, *W3h, *W3l;
    cudaGetSymbolAddress((void**)&bufA, g_bufA);
    cudaGetSymbolAddress((void**)&bufB, g_bufB);
    cudaGetSymbolAddress((void**)&bufC, g_bufC);
    cudaGetSymbolAddress((void**)&acc1, g_acc1);
    cudaGetSymbolAddress((void**)&acc2, g_acc2);
    cudaGetSymbolAddress((void**)&AhiA, g_AhiA);
    cudaGetSymbolAddress((void**)&AloA, g_AloA);
    cudaGetSymbolAddress((void**)&AhiB, g_AhiB);
    cudaGetSymbolAddress((void**)&AloB, g_AloB);
    cudaGetSymbolAddress((void**)&W1h, g_W1h);
    cudaGetSymbolAddress((void**)&W1l, g_W1l);
    cudaGetSymbolAddress((void**)&W2h, g_W2h);
    cudaGetSymbolAddress((void**)&W2l, g_W2l);
    cudaGetSymbolAddress((void**)&W3h, g_W3h);
    cudaGetSymbolAddress((void**)&W3l, g_W3l);

    cudaFuncSetAttribute(gemm_fused_kernel,
                         cudaFuncAttributeMaxDynamicSharedMemorySize, SMEM_TOTAL_GEMM);

    // ---- graph setup (4 launches; scan computes dis) ----
    zero_counts_kernel<<<(N_NODES + 255) / 256, 256>>>();
    hist_kernel<<<(N_EDGES + 255) / 256, 256>>>(row, col);
    scan_kernel<<<1, 1024>>>();
    scatter_kernel<<<(N_EDGES + 255) / 256, 256>>>(row, col);

    // ================= Layer 1: 1152 -> 1152, K=6, Kcat=6912 =================
    // prop1 also splits x itself into slice 0 (selfColOff = 0)
    prop_kernel<F1, 96><<<M_PAD, 96>>>(x,    nullptr, bufA, AhiA, AloA, KCAT1, 1 * F1, 1.0f, 0);
    prop_kernel<F1, 96><<<M_PAD, 96>>>(bufA, x,       bufB, AhiA, AloA, KCAT1, 2 * F1, 2.0f, -1);
    prop_kernel<F1, 96><<<M_PAD, 96>>>(bufB, bufA,    bufC, AhiA, AloA, KCAT1, 3 * F1, 2.0f, -1);
    prop_kernel<F1, 96><<<M_PAD, 96>>>(bufC, bufB,    bufA, AhiA, AloA, KCAT1, 4 * F1, 2.0f, -1);
    prop_kernel<F1, 96><<<M_PAD, 96>>>(bufA, bufC,    nullptr, AhiA, AloA, KCAT1, 5 * F1, 2.0f, -1);

    // ---- weight conversions ----
    {
        dim3 g1((KCAT1 + 31) / 32, (N1PAD + 31) / 32);
        wsplit_kernel<<<g1, dim3(32, 8)>>>(W1, KCAT1, F1, N1PAD, W1h, W1l);
        dim3 g2((KCAT2 + 31) / 32, (N2PAD + 31) / 32);
        wsplit_kernel<<<g2, dim3(32, 8)>>>(W2, KCAT2, F2, N2PAD, W2h, W2l);
        dim3 g3((KCAT3 + 31) / 32, (N3PAD + 31) / 32);
        wsplit_kernel<<<g3, dim3(32, 8)>>>(W3, KCAT3, F3, N3PAD, W3h, W3l);
    }

    {
        dim3 grid(N1PAD / 128, M_PAD / 128);
        gemm_fused_kernel<<<grid, 128, SMEM_TOTAL_GEMM>>>(
            AhiA, AloA, W1h, W1l, b1, acc1, F1, KCAT1, AhiB, AloB, KCAT2);
    }

    // ================= Layer 2: 1152 -> 576, K=5, Kcat=5760 =================
    prop_kernel<F1, 96><<<M_PAD, 96>>>(acc1, nullptr, bufA, AhiB, AloB, KCAT2, 1 * F1, 1.0f, -1);
    prop_kernel<F1, 96><<<M_PAD, 96>>>(bufA, acc1,    bufB, AhiB, AloB, KCAT2, 2 * F1, 2.0f, -1);
    prop_kernel<F1, 96><<<M_PAD, 96>>>(bufB, bufA,    bufC, AhiB, AloB, KCAT2, 3 * F1, 2.0f, -1);
    prop_kernel<F1, 96><<<M_PAD, 96>>>(bufC, bufB,    nullptr, AhiB, AloB, KCAT2, 4 * F1, 2.0f, -1);
    {
        dim3 grid(N2PAD / 128, M_PAD / 128);
        gemm_fused_kernel<<<grid, 128, SMEM_TOTAL_GEMM>>>(
            AhiB, AloB, W2h, W2l, b2, acc2, F2, KCAT2, AhiA, AloA, KCAT3);
    }

    // ================= Layer 3: 576 -> 288, K=5, Kcat=2880 =================
    prop_kernel<F2, 144><<<M_PAD, 144>>>(acc2, nullptr, bufA, AhiA, AloA, KCAT3, 1 * F2, 1.0f, -1);
    prop_kernel<F2, 144><<<M_PAD, 144>>>(bufA, acc2,    bufB, AhiA, AloA, KCAT3, 2 * F2, 2.0f, -1);
    prop_kernel<F2, 144><<<M_PAD, 144>>>(bufB, bufA,    bufC, AhiA, AloA, KCAT3, 3 * F2, 2.0f, -1);
    prop_kernel<F2, 144><<<M_PAD, 144>>>(bufC, bufB,    nullptr, AhiA, AloA, KCAT3, 4 * F2, 2.0f, -1);
    {
        dim3 grid(N3PAD / 128, M_PAD / 128);
        gemm_fused_kernel<<<grid, 128, SMEM_TOTAL_GEMM>>>(
            AhiA, AloA, W3h, W3l, b3, out, F3, KCAT3, nullptr, nullptr, 0);
    }
}

// round 10
// speedup vs baseline: 1.6475x; 1.1177x over previous
#include <cuda_runtime.h>
#include <cuda_bf16.h>
#include <cstdint>
#include <cstddef>

#define N_NODES 20000
#define N_EDGES 320000
#define M_PAD   20224          // 158 * 128
#define F1 1152
#define F2 576
#define F3 288

// GEMM output (Y-cat) dims: N = K*Fout, padded to /128
#define NY1 6912               // 6*1152, 54*128 exact
#define NY2 2880               // 5*576
#define NY2P 2944              // 23*128
#define NY3 1440               // 5*288
#define NY3P 1536              // 12*128

// ---------------- scratch (device globals; allocation-free) ----------------
__device__ float g_Y[(size_t)M_PAD * NY1];          // Y-cat (max size, reused per layer)
__device__ float g_bufA[(size_t)M_PAD * F1];        // Clenshaw b buffers
__device__ float g_bufB[(size_t)M_PAD * F1];
__device__ float g_bufC[(size_t)M_PAD * F1];

__device__ __nv_bfloat16 g_A1h[(size_t)M_PAD * F1]; // GEMM A ping-pong (split)
__device__ __nv_bfloat16 g_A1l[(size_t)M_PAD * F1];
__device__ __nv_bfloat16 g_A2h[(size_t)M_PAD * F1];
__device__ __nv_bfloat16 g_A2l[(size_t)M_PAD * F1];

__device__ __nv_bfloat16 g_W1h[(size_t)NY1 * F1];   // B = Wcat^T splits [K*Fout x Fin]
__device__ __nv_bfloat16 g_W1l[(size_t)NY1 * F1];
__device__ __nv_bfloat16 g_W2h[(size_t)NY2P * F1];
__device__ __nv_bfloat16 g_W2l[(size_t)NY2P * F1];
__device__ __nv_bfloat16 g_W3h[(size_t)NY3P * F2];
__device__ __nv_bfloat16 g_W3l[(size_t)NY3P * F2];

__device__ int   g_deg[N_NODES];
__device__ int   g_fill[N_NODES];
__device__ int   g_rowptr[N_NODES + 1];
__device__ int   g_colS[N_EDGES];
__device__ float g_dis[N_NODES];

// ---------------- PTX helpers (base sm_103 target only) ----------------
__device__ __forceinline__ uint32_t smem_u32(const void* p) {
    uint32_t a;
    asm("{ .reg .u64 t; cvta.to.shared.u64 t, %1; cvt.u32.u64 %0, t; }" : "=r"(a) : "l"(p));
    return a;
}

#define CP_ASYNC16(dst, src) \
    asm volatile("cp.async.cg.shared.global [%0], [%1], 16;" :: "r"(dst), "l"(src) : "memory")
#define CP_COMMIT() asm volatile("cp.async.commit_group;" ::: "memory")
#define CP_WAIT1()  asm volatile("cp.async.wait_group 1;" ::: "memory")

#define LDMATRIX_X4(r0, r1, r2, r3, addr) \
    asm volatile("ldmatrix.sync.aligned.m8n8.x4.shared.b16 {%0,%1,%2,%3}, [%4];" \
                 : "=r"(r0), "=r"(r1), "=r"(r2), "=r"(r3) : "r"(addr))

#define MMA_BF16(d, a, b) \
    asm volatile("mma.sync.aligned.m16n8k16.row.col.f32.bf16.bf16.f32 " \
                 "{%0,%1,%2,%3}, {%4,%5,%6,%7}, {%8,%9}, {%0,%1,%2,%3};" \
                 : "+f"((d)[0]), "+f"((d)[1]), "+f"((d)[2]), "+f"((d)[3]) \
                 : "r"((a)[0]), "r"((a)[1]), "r"((a)[2]), "r"((a)[3]), \
                   "r"((b)[0]), "r"((b)[1]))

// ---------------- graph setup ----------------
__global__ void zero_counts_kernel() {
    int i = blockIdx.x * blockDim.x + threadIdx.x;
    if (i < N_NODES) { g_deg[i] = 0; g_fill[i] = 0; }
}
__global__ void hist_kernel(const int* __restrict__ row, const int* __restrict__ col) {
    int e = blockIdx.x * blockDim.x + threadIdx.x;
    if (e < N_EDGES) {
        int r = row[e];
        if (r != col[e]) atomicAdd(&g_deg[r], 1);
    }
}
// scan + dis fused
__global__ void scan_kernel() {
    __shared__ int sums[1024];
    int t = threadIdx.x;
    const int CHUNK = (N_NODES + 1023) / 1024;
    int lo = t * CHUNK, hi = lo + CHUNK;
    if (hi > N_NODES) hi = N_NODES;
    int s = 0;
    for (int i = lo; i < hi; i++) s += g_deg[i];
    sums[t] = s;
    __syncthreads();
    for (int off = 1; off < 1024; off <<= 1) {
        int v = (t >= off) ? sums[t - off] : 0;
        __syncthreads();
        sums[t] += v;
        __syncthreads();
    }
    int run = (t == 0) ? 0 : sums[t - 1];
    for (int i = lo; i < hi; i++) {
        g_rowptr[i] = run;
        int d = g_deg[i];
        run += d;
        g_dis[i] = (d > 0) ? rsqrtf((float)d) : 0.0f;
    }
    if (t == 1023) g_rowptr[N_NODES] = sums[1023];
}
__global__ void scatter_kernel(const int* __restrict__ row, const int* __restrict__ col) {
    int e = blockIdx.x * blockDim.x + threadIdx.x;
    if (e < N_EDGES) {
        int r = row[e], c = col[e];
        if (r != c) {
            int pos = g_rowptr[r] + atomicAdd(&g_fill[r], 1);
            g_colS[pos] = c;
        }
    }
}

// ---------------- split helpers ----------------
__device__ __forceinline__ void split1(float v, __nv_bfloat16& h, __nv_bfloat16& l) {
    h = __float2bfloat16(v);
    l = __float2bfloat16(v - __bfloat162float(h));
}

// convert x (fp32 [M x F]) into A split; zero pad rows
__global__ void convert_split_kernel(const float* __restrict__ src, int F,
                                     __nv_bfloat16* __restrict__ hi,
                                     __nv_bfloat16* __restrict__ lo) {
    int total = M_PAD * F;
    for (int idx = blockIdx.x * blockDim.x + threadIdx.x; idx < total;
         idx += gridDim.x * blockDim.x) {
        int r = idx / F, c = idx - r * F;
        float v = (r < N_NODES) ? src[(size_t)r * F + c] : 0.0f;
        __nv_bfloat16 h, l;
        split1(v, h, l);
        size_t o = (size_t)r * F + c;
        hi[o] = h; lo[o] = l;
    }
}

// weight transpose+split into cat-B: B[(k*Fout + n)][kk] = W[k][kk][n]
// W is [K][Fin][Fout] fp32. Grid (Fin/32, Fout/32, K). Block (32,8).
__global__ void wsplit2_kernel(const float* __restrict__ W, int Fin, int Fout,
                               __nv_bfloat16* __restrict__ hi,
                               __nv_bfloat16* __restrict__ lo) {
    __shared__ float tile[32][33];
    int kk0 = blockIdx.x * 32, n0 = blockIdx.y * 32, k = blockIdx.z;
    int tx = threadIdx.x, ty = threadIdx.y;
    const float* Wk = W + (size_t)k * Fin * Fout;
#pragma unroll
    for (int r = 0; r < 32; r += 8)
        tile[ty + r][tx] = Wk[(size_t)(kk0 + ty + r) * Fout + n0 + tx];
    __syncthreads();
#pragma unroll
    for (int r = 0; r < 32; r += 8) {
        float v = tile[tx][ty + r];
        __nv_bfloat16 h, l;
        split1(v, h, l);
        size_t o = (size_t)(k * Fout + n0 + ty + r) * Fin + kk0 + tx;
        hi[o] = h; lo[o] = l;
    }
}

// ---------------- Clenshaw propagation ----------------
// out = alpha*(L~ g) + addY - sub   (sub nullable)
// MID:   write fp32 out (all M_PAD rows; pad rows produce 0)
// FINAL: r = real ? relu(r + bias) : 0; write bf16 hi/lo split (if hi != null)
//        and fp32 outF guarded to i < N_NODES (if outF != null)
// All row strides given in float4 units; gather/add/sub pointers pre-offset.
template <int F, int THREADS, bool FINAL>
__global__ void prop2_kernel(const float* __restrict__ g, int ldG4,
                             const float* __restrict__ addY, int ldA4,
                             const float* __restrict__ sub, int ldS4,
                             float alpha,
                             float* __restrict__ outF, int ldO4,
                             const float* __restrict__ bias,
                             __nv_bfloat16* __restrict__ hi,
                             __nv_bfloat16* __restrict__ lo, int ldCat) {
    constexpr int F4 = F / 4;
    constexpr int NF = F4 / THREADS;
    static_assert(NF * THREADS == F4, "exact fit required");
    constexpr int ECHUNK = 128;
    __shared__ int   s_col[ECHUNK];
    __shared__ float s_w[ECHUNK];

    int i = blockIdx.x;
    int tid = threadIdx.x;
    bool real = (i < N_NODES);
    int s0 = real ? g_rowptr[i] : 0;
    int s1 = real ? g_rowptr[i + 1] : 0;

    float ax[NF], ay[NF], az[NF], aw[NF];
#pragma unroll
    for (int j = 0; j < NF; j++) { ax[j] = 0.f; ay[j] = 0.f; az[j] = 0.f; aw[j] = 0.f; }

    int e = s0;
    while (e < s1) {
        int cnt = s1 - e; if (cnt > ECHUNK) cnt = ECHUNK;
        __syncthreads();
        for (int q = tid; q < cnt; q += THREADS) {
            int c = g_colS[e + q];
            s_col[q] = c;
            s_w[q] = g_dis[c];
        }
        __syncthreads();

        int q = 0;
        for (; q + 2 <= cnt; q += 2) {
            int c0 = s_col[q], c1 = s_col[q + 1];
            float w0 = s_w[q], w1 = s_w[q + 1];
            const float4* t0 = reinterpret_cast<const float4*>(g) + (size_t)c0 * ldG4;
            const float4* t1 = reinterpret_cast<const float4*>(g) + (size_t)c1 * ldG4;
#pragma unroll
            for (int j = 0; j < NF; j++) {
                int f = tid + j * THREADS;
                float4 v0 = t0[f];
                float4 v1 = t1[f];
                ax[j] += w0 * v0.x + w1 * v1.x;
                ay[j] += w0 * v0.y + w1 * v1.y;
                az[j] += w0 * v0.z + w1 * v1.z;
                aw[j] += w0 * v0.w + w1 * v1.w;
            }
        }
        if (q < cnt) {
            int c = s_col[q];
            float s = s_w[q];
            const float4* tr = reinterpret_cast<const float4*>(g) + (size_t)c * ldG4;
#pragma unroll
            for (int j = 0; j < NF; j++) {
                int f = tid + j * THREADS;
                float4 v = tr[f];
                ax[j] += s * v.x; ay[j] += s * v.y;
                az[j] += s * v.z; aw[j] += s * v.w;
            }
        }
        e += cnt;
    }

    float sc = real ? (-alpha * g_dis[i]) : 0.0f;
    const float4* arow = reinterpret_cast<const float4*>(addY) + (size_t)i * ldA4;
    const float4* srow = sub ? (reinterpret_cast<const float4*>(sub) + (size_t)i * ldS4) : nullptr;

#pragma unroll
    for (int j = 0; j < NF; j++) {
        int f = tid + j * THREADS;
        float4 av = arow[f];
        float4 r;
        r.x = sc * ax[j] + av.x; r.y = sc * ay[j] + av.y;
        r.z = sc * az[j] + av.z; r.w = sc * aw[j] + av.w;
        if (srow) {
            float4 sv = srow[f];
            r.x -= sv.x; r.y -= sv.y; r.z -= sv.z; r.w -= sv.w;
        }
        if (FINAL) {
            if (real) {
                const float4 bv = reinterpret_cast<const float4*>(bias)[f];
                r.x = fmaxf(r.x + bv.x, 0.f); r.y = fmaxf(r.y + bv.y, 0.f);
                r.z = fmaxf(r.z + bv.z, 0.f); r.w = fmaxf(r.w + bv.w, 0.f);
            } else {
                r.x = r.y = r.z = r.w = 0.f;
            }
            if (hi) {
                __nv_bfloat16 hx, lx, hy, ly, hz, lz, hw, lw;
                split1(r.x, hx, lx); split1(r.y, hy, ly);
                split1(r.z, hz, lz); split1(r.w, hw, lw);
                size_t o = (size_t)i * ldCat + (size_t)f * 4;
                __nv_bfloat162* hp = reinterpret_cast<__nv_bfloat162*>(hi + o);
                __nv_bfloat162* lp = reinterpret_cast<__nv_bfloat162*>(lo + o);
                hp[0] = __nv_bfloat162(hx, hy); hp[1] = __nv_bfloat162(hz, hw);
                lp[0] = __nv_bfloat162(lx, ly); lp[1] = __nv_bfloat162(lz, lw);
            }
            if (outF && real)
                reinterpret_cast<float4*>(outF)[(size_t)i * ldO4 + f] = r;
        } else {
            reinterpret_cast<float4*>(outF)[(size_t)i * ldO4 + f] = r;
        }
    }
}

// ---------------- fused tri-product mma.sync GEMM ----------------
// Y[M x N] (fp32, ld=ldC) = [Ahi|Alo] x [Bhi|Blo]^T tri-product.
// A: [M_PAD x K] bf16. B: [Npad x K] bf16 (pad rows garbage, cols >= N discarded).
// 128x128 CTA, 4 warps of 64x64, 3 stages XOR-swizzled, 1 sync/k-tile, 2 CTA/SM.
#define GBK     32
#define TILE_B  (128 * 64)
#define STG_B   (4 * TILE_B)
#define SMEM_TOTAL_GEMM (3 * STG_B)       // 98304

__device__ __forceinline__ uint32_t sw_off(int r, int c16) {
    return (uint32_t)(r * 64 + ((c16 ^ ((r >> 1) & 3)) * 16));
}

__global__ void __launch_bounds__(128, 2)
gemm_fused_kernel(const __nv_bfloat16* __restrict__ Ahi, const __nv_bfloat16* __restrict__ Alo,
                  const __nv_bfloat16* __restrict__ Bhi, const __nv_bfloat16* __restrict__ Blo,
                  float* __restrict__ C, int N, int ldC, int K) {
    extern __shared__ char smem[];
    uint32_t sb = smem_u32(smem);
    int tid = threadIdx.x;
    int lane = tid & 31;
    int wid = tid >> 5;
    int bm = blockIdx.y * 128;
    int bn = blockIdx.x * 128;

    const int kt = K / GBK;

    int wm = (wid & 1) * 64;
    int wn = (wid >> 1) * 64;

    float d[4][8][4];
#pragma unroll
    for (int i = 0; i < 4; i++)
#pragma unroll
        for (int j = 0; j < 8; j++)
#pragma unroll
            for (int q = 0; q < 4; q++) d[i][j][q] = 0.f;

    size_t ld = (size_t)K * 2;   // bytes per row
    auto issue = [&](int it) {
        int kk = it * GBK;
        int s = it % 3;
        uint32_t base = sb + s * STG_B;
        const char* src[4] = {
            (const char*)(Ahi + (size_t)bm * K + kk),
            (const char*)(Alo + (size_t)bm * K + kk),
            (const char*)(Bhi + (size_t)bn * K + kk),
            (const char*)(Blo + (size_t)bn * K + kk)
        };
#pragma unroll
        for (int tIdx = 0; tIdx < 4; tIdx++) {
            uint32_t dst = base + tIdx * TILE_B;
            const char* gp = src[tIdx];
#pragma unroll
            for (int i = 0; i < 4; i++) {
                int v = tid + i * 128;
                int r = v >> 2, p = v & 3;
                CP_ASYNC16(dst + sw_off(r, p), gp + (size_t)r * ld + p * 16);
            }
        }
    };

    issue(0); CP_COMMIT();
    if (kt > 1) issue(1);
    CP_COMMIT();

    int lrow = lane & 15;
    int lcol = (lane >> 4) * 8;

    uint32_t arow[4], brow[4];
#pragma unroll
    for (int i = 0; i < 4; i++) {
        int rr = wm + i * 16 + lrow;
        arow[i] = (uint32_t)(rr * 64) | ((uint32_t)((rr >> 1) & 3) << 28);
    }
#pragma unroll
    for (int jp = 0; jp < 4; jp++) {
        int rr = wn + jp * 16 + lrow;
        brow[jp] = (uint32_t)(rr * 64) | ((uint32_t)((rr >> 1) & 3) << 28);
    }

    for (int it = 0; it < kt; ++it) {
        CP_WAIT1();
        __syncthreads();

        if (it + 2 < kt) issue(it + 2);
        CP_COMMIT();

        int s = it % 3;
        uint32_t sAh = sb + s * STG_B;
        uint32_t sAl = sAh + TILE_B;
        uint32_t sBh = sAh + 2 * TILE_B;
        uint32_t sBl = sAh + 3 * TILE_B;

#pragma unroll
        for (int ks = 0; ks < GBK; ks += 16) {
            uint32_t cch = (uint32_t)((ks + lcol) >> 3);

            uint32_t ah[4][4], bh[8][2];
#pragma unroll
            for (int i = 0; i < 4; i++) {
                uint32_t off = (arow[i] & 0x0fffffffu) + ((cch ^ (arow[i] >> 28)) << 4);
                LDMATRIX_X4(ah[i][0], ah[i][1], ah[i][2], ah[i][3], sAh + off);
            }
#pragma unroll
            for (int jp = 0; jp < 4; jp++) {
                uint32_t off = (brow[jp] & 0x0fffffffu) + ((cch ^ (brow[jp] >> 28)) << 4);
                uint32_t q0, q1, q2, q3;
                LDMATRIX_X4(q0, q1, q2, q3, sBh + off);
                bh[2 * jp][0] = q0; bh[2 * jp][1] = q2;
                bh[2 * jp + 1][0] = q1; bh[2 * jp + 1][1] = q3;
            }
#pragma unroll
            for (int i = 0; i < 4; i++)
#pragma unroll
                for (int j = 0; j < 8; j++)
                    MMA_BF16(d[i][j], ah[i], bh[j]);

            {
                uint32_t al[4][4];
#pragma unroll
                for (int i = 0; i < 4; i++) {
                    uint32_t off = (arow[i] & 0x0fffffffu) + ((cch ^ (arow[i] >> 28)) << 4);
                    LDMATRIX_X4(al[i][0], al[i][1], al[i][2], al[i][3], sAl + off);
                }
#pragma unroll
                for (int i = 0; i < 4; i++)
#pragma unroll
                    for (int j = 0; j < 8; j++)
                        MMA_BF16(d[i][j], al[i], bh[j]);
            }

            {
                uint32_t bl[8][2];
#pragma unroll
                for (int jp = 0; jp < 4; jp++) {
                    uint32_t off = (brow[jp] & 0x0fffffffu) + ((cch ^ (brow[jp] >> 28)) << 4);
                    uint32_t q0, q1, q2, q3;
                    LDMATRIX_X4(q0, q1, q2, q3, sBl + off);
                    bl[2 * jp][0] = q0; bl[2 * jp][1] = q2;
                    bl[2 * jp + 1][0] = q1; bl[2 * jp + 1][1] = q3;
                }
#pragma unroll
                for (int i = 0; i < 4; i++)
#pragma unroll
                    for (int j = 0; j < 8; j++)
                        MMA_BF16(d[i][j], ah[i], bl[j]);
            }
        }
    }

    // epilogue: plain fp32 Y writes (pad rows of A are zero -> Y pad rows zero)
    int gr = lane >> 2;
    int gc = (lane & 3) * 2;
#pragma unroll
    for (int i = 0; i < 4; i++) {
#pragma unroll
        for (int j = 0; j < 8; j++) {
            int colb = bn + wn + j * 8 + gc;
            if (colb >= N) continue;
            int row0 = bm + wm + i * 16 + gr;
            int row1 = row0 + 8;
            float2 v0; v0.x = d[i][j][0]; v0.y = d[i][j][1];
            float2 v1; v1.x = d[i][j][2]; v1.y = d[i][j][3];
            *reinterpret_cast<float2*>(&C[(size_t)row0 * ldC + colb]) = v0;
            *reinterpret_cast<float2*>(&C[(size_t)row1 * ldC + colb]) = v1;
        }
    }
}

// ---------------- host orchestration ----------------
extern "C" void kernel_launch(void* const* d_in, const int* in_sizes, int n_in,
                              void* d_out, int out_size) {
    const float* x   = (const float*)d_in[0];
    const int*   row = (const int*)d_in[1];
    const int*   col = (const int*)d_in[2];
    const float* W1  = (const float*)d_in[3];
    const float* b1  = (const float*)d_in[4];
    const float* W2  = (const float*)d_in[5];
    const float* b2  = (const float*)d_in[6];
    const float* W3  = (const float*)d_in[7];
    const float* b3  = (const float*)d_in[8];
    float* out = (float*)d_out;

    float *Y, *bufA, *bufB, *bufC;
    __nv_bfloat16 *A1h, *A1l, *A2h, *A2l;
    __nv_bfloat16 *W1h, *W1l, *W2h, *W2l, *W3h, *W3l;
    cudaGetSymbolAddress((void**)&Y, g_Y);
    cudaGetSymbolAddress((void**)&bufA, g_bufA);
    cudaGetSymbolAddress((void**)&bufB, g_bufB);
    cudaGetSymbolAddress((void**)&bufC, g_bufC);
    cudaGetSymbolAddress((void**)&A1h, g_A1h);
    cudaGetSymbolAddress((void**)&A1l, g_A1l);
    cudaGetSymbolAddress((void**)&A2h, g_A2h);
    cudaGetSymbolAddress((void**)&A2l, g_A2l);
    cudaGetSymbolAddress((void**)&W1h, g_W1h);
    cudaGetSymbolAddress((void**)&W1l, g_W1l);
    cudaGetSymbolAddress((void**)&W2h, g_W2h);
    cudaGetSymbolAddress((void**)&W2l, g_W2l);
    cudaGetSymbolAddress((void**)&W3h, g_W3h);
    cudaGetSymbolAddress((void**)&W3l, g_W3l);

    cudaFuncSetAttribute(gemm_fused_kernel,
                         cudaFuncAttributeMaxDynamicSharedMemorySize, SMEM_TOTAL_GEMM);

    // ---- graph setup ----
    zero_counts_kernel<<<(N_NODES + 255) / 256, 256>>>();
    hist_kernel<<<(N_EDGES + 255) / 256, 256>>>(row, col);
    scan_kernel<<<1, 1024>>>();
    scatter_kernel<<<(N_EDGES + 255) / 256, 256>>>(row, col);

    // ---- conversions ----
    convert_split_kernel<<<4096, 256>>>(x, F1, A1h, A1l);
    wsplit2_kernel<<<dim3(F1 / 32, F1 / 32, 6), dim3(32, 8)>>>(W1, F1, F1, W1h, W1l);
    wsplit2_kernel<<<dim3(F1 / 32, F2 / 32, 5), dim3(32, 8)>>>(W2, F1, F2, W2h, W2l);
    wsplit2_kernel<<<dim3(F2 / 32, F3 / 32, 5), dim3(32, 8)>>>(W3, F2, F3, W3h, W3l);

    // ================= Layer 1: K=6, Fout=1152 =================
    // Y = x @ W1cat^T : [M x 6912]
    gemm_fused_kernel<<<dim3(NY1 / 128, M_PAD / 128), 128, SMEM_TOTAL_GEMM>>>(
        A1h, A1l, W1h, W1l, Y, NY1, NY1, F1);
    {
        const int ldY = NY1 / 4;        // float4 stride = 1728
        const int ldF = F1 / 4;         // 288
        // Clenshaw: b5 = Y5; b4..b1; S = Y0 + L~b1 - b2
        prop2_kernel<F1, 96, false><<<M_PAD, 96>>>(Y + 5 * F1, ldY, Y + 4 * F1, ldY,
                                                   nullptr, 0, 2.0f, bufA, ldF,
                                                   nullptr, nullptr, nullptr, 0);
        prop2_kernel<F1, 96, false><<<M_PAD, 96>>>(bufA, ldF, Y + 3 * F1, ldY,
                                                   Y + 5 * F1, ldY, 2.0f, bufB, ldF,
                                                   nullptr, nullptr, nullptr, 0);
        prop2_kernel<F1, 96, false><<<M_PAD, 96>>>(bufB, ldF, Y + 2 * F1, ldY,
                                                   bufA, ldF, 2.0f, bufC, ldF,
                                                   nullptr, nullptr, nullptr, 0);
        prop2_kernel<F1, 96, false><<<M_PAD, 96>>>(bufC, ldF, Y + 1 * F1, ldY,
                                                   bufB, ldF, 2.0f, bufA, ldF,
                                                   nullptr, nullptr, nullptr, 0);
        prop2_kernel<F1, 96, true ><<<M_PAD, 96>>>(bufA, ldF, Y + 0, ldY,
                                                   bufC, ldF, 1.0f, nullptr, 0,
                                                   b1, A2h, A2l, F1);
    }

    // ================= Layer 2: K=5, Fout=576 =================
    gemm_fused_kernel<<<dim3(NY2P / 128, M_PAD / 128), 128, SMEM_TOTAL_GEMM>>>(
        A2h, A2l, W2h, W2l, Y, NY2, NY2P, F1);
    {
        const int ldY = NY2P / 4;       // 736
        const int ldF = F2 / 4;         // 144
        prop2_kernel<F2, 144, false><<<M_PAD, 144>>>(Y + 4 * F2, ldY, Y + 3 * F2, ldY,
                                                     nullptr, 0, 2.0f, bufA, ldF,
                                                     nullptr, nullptr, nullptr, 0);
        prop2_kernel<F2, 144, false><<<M_PAD, 144>>>(bufA, ldF, Y + 2 * F2, ldY,
                                                     Y + 4 * F2, ldY, 2.0f, bufB, ldF,
                                                     nullptr, nullptr, nullptr, 0);
        prop2_kernel<F2, 144, false><<<M_PAD, 144>>>(bufB, ldF, Y + 1 * F2, ldY,
                                                     bufA, ldF, 2.0f, bufC, ldF,
                                                     nullptr, nullptr, nullptr, 0);
        prop2_kernel<F2, 144, true ><<<M_PAD, 144>>>(bufC, ldF, Y + 0, ldY,
                                                     bufB, ldF, 1.0f, nullptr, 0,
                                                     b2, A1h, A1l, F2);
    }

    // ================= Layer 3: K=5, Fout=288 =================
    gemm_fused_kernel<<<dim3(NY3P / 128, M_PAD / 128), 128, SMEM_TOTAL_GEMM>>>(
        A1h, A1l, W3h, W3l, Y, NY3, NY3P, F2);
    {
        const int ldY = NY3P / 4;       // 384
        const int ldF = F3 / 4;         // 72
        prop2_kernel<F3, 72, false><<<M_PAD, 72>>>(Y + 4 * F3, ldY, Y + 3 * F3, ldY,
                                                   nullptr, 0, 2.0f, bufA, ldF,
                                                   nullptr, nullptr, nullptr, 0);
        prop2_kernel<F3, 72, false><<<M_PAD, 72>>>(bufA, ldF, Y + 2 * F3, ldY,
                                                   Y + 4 * F3, ldY, 2.0f, bufB, ldF,
                                                   nullptr, nullptr, nullptr, 0);
        prop2_kernel<F3, 72, false><<<M_PAD, 72>>>(bufB, ldF, Y + 1 * F3, ldY,
                                                   bufA, ldF, 2.0f, bufC, ldF,
                                                   nullptr, nullptr, nullptr, 0);
        prop2_kernel<F3, 72, true ><<<M_PAD, 72>>>(bufC, ldF, Y + 0, ldY,
                                                   bufB, ldF, 1.0f, out, ldF,
                                                   b3, nullptr, nullptr, 0);
    }
}